// round 15
// baseline (speedup 1.0000x reference)
#include <cuda_runtime.h>
#include <cuda_bf16.h>

#define BB 8
#define TT 64
#define NN 2048
#define GG 192
#define EE 32768
#define NBLK 296
#define WSZ (2048ULL*192*64)

// ---------------- device scratch ----------------
__device__ unsigned short g_Wih[WSZ];        // bf16 [n][g][k] (native layout)
__device__ unsigned short g_Whh[WSZ];
__device__ float g_Wmix_t[128*64];           // [k][h]
__device__ float g_Wmsg_t[64*64];            // [k][h]
__device__ float g_m[2][(size_t)BB*NN*64];   // messages [b][n][h]
__device__ int   g_deg[NN];
__device__ int   g_rowptr[NN+1];
__device__ int   g_csrc[EE];
__device__ float g_losspart[NN];
__device__ int   g_maskcnt;
__device__ int   g_masktype;
__device__ unsigned g_cnt0[37];
__device__ unsigned g_cnt1;
__device__ unsigned g_gen;

__device__ __forceinline__ int mask_at(const void* m, size_t i, int mt) {
    if (mt == 2) return ((const float*)m)[i] != 0.f;
    if (mt == 1) return ((const int*)m)[i]   != 0;
    return ((const unsigned char*)m)[i] != 0;
}

#define FMA2(d, a, b) asm("fma.rn.f32x2 %0, %1, %2, %3;" : "=l"(d) : "l"(a), "l"(b), "l"(d))
#define SPLAT2(d, w)  asm("mov.b64 %0, {%1, %1};" : "=l"(d) : "r"(w))
#define SPLATF(d, f)  asm("mov.b64 %0, {%1, %1};" : "=l"(d) : "f"(f))
#define UNPK2(lo, hi, v) asm("mov.b64 {%0, %1}, %2;" : "=f"(lo), "=f"(hi) : "l"(v))

__device__ __forceinline__ float fast_tanh(float x) {
    float y; asm("tanh.approx.f32 %0, %1;" : "=f"(y) : "f"(x)); return y;
}
__device__ __forceinline__ float fast_sig(float x) {
    return 0.5f + 0.5f * fast_tanh(0.5f * x);
}

__device__ __forceinline__ unsigned ld_vol(unsigned* p) {
    unsigned v; asm volatile("ld.volatile.global.u32 %0, [%1];" : "=r"(v) : "l"(p)); return v;
}

// generation-target grid barrier: 296 blocks = 37 groups x 8
__device__ __forceinline__ void grid_barrier(int bid, int tid, unsigned tgt) {
    __syncthreads();
    if (tid == 0) {
        __threadfence();
        unsigned r = atomicAdd(&g_cnt0[bid >> 3], 1u);
        if (r == 7u) {
            unsigned r2 = atomicAdd(&g_cnt1, 1u);
            if (r2 == 36u) {
                g_cnt1 = 0u;
                #pragma unroll
                for (int i = 0; i < 37; ++i) g_cnt0[i] = 0u;
                __threadfence();
                atomicExch(&g_gen, tgt);
            }
        }
        while (ld_vol(&g_gen) < tgt) __nanosleep(64);
        __threadfence();
    }
    __syncthreads();
}

// ---------------- prologue kernels (packed so k_persist is launch #3) ----------------
__global__ void k_cvt(const float* __restrict__ Wih, const float* __restrict__ Whh) {
    if (blockIdx.x == 0) {
        for (int i = threadIdx.x; i < NN; i += 256) g_deg[i] = 0;
        if (threadIdx.x == 0) {
            g_maskcnt = 0; g_cnt1 = 0u; g_gen = 0u;
            for (int i = 0; i < 37; ++i) g_cnt0[i] = 0u;
        }
    }
    for (size_t i = (size_t)blockIdx.x*256 + threadIdx.x; i < WSZ/8; i += 4096ull*256) {
        #pragma unroll
        for (int a = 0; a < 2; ++a) {
            const float4* src = (const float4*)(a ? Whh : Wih) + i*2;
            float4 f0 = src[0], f1 = src[1];
            __nv_bfloat162 p0 = __floats2bfloat162_rn(f0.x, f0.y);
            __nv_bfloat162 p1 = __floats2bfloat162_rn(f0.z, f0.w);
            __nv_bfloat162 p2 = __floats2bfloat162_rn(f1.x, f1.y);
            __nv_bfloat162 p3 = __floats2bfloat162_rn(f1.z, f1.w);
            uint4 o;
            o.x = *(unsigned*)&p0; o.y = *(unsigned*)&p1;
            o.z = *(unsigned*)&p2; o.w = *(unsigned*)&p3;
            ((uint4*)(a ? g_Whh : g_Wih))[i] = o;
        }
    }
}

__global__ void k_init(const float* __restrict__ b_msg, const unsigned* __restrict__ maskw,
                       const float* __restrict__ Wmix, const float* __restrict__ Wmsg,
                       const int* __restrict__ ei) {
    int tid = threadIdx.x;
    if (blockIdx.x < 4096) {
        int i = blockIdx.x*256 + tid;
        g_m[0][i] = b_msg[i & 63];
        if (i < NN) g_losspart[i] = 0.f;
        if (i < EE) atomicAdd(&g_deg[ei[EE + i]], 1);   // degree count
    } else {
        for (int i = tid; i < 128*64; i += 256) {
            int k = i >> 6, h = i & 63;
            g_Wmix_t[i] = Wmix[h*128 + k];
        }
        for (int i = tid; i < 64*64; i += 256) {
            int k = i >> 6, h = i & 63;
            g_Wmsg_t[i] = Wmsg[h*64 + k];
        }
        __shared__ int sI, sF;
        if (tid == 0) { sI = 1; sF = 1; }
        __syncthreads();
        int okI = 1, okF = 1;
        for (int i = tid; i < 4096; i += 256) {
            unsigned v = maskw[i];
            okI &= (v <= 1u) ? 1 : 0;
            okF &= (v == 0u || v == 0x3F800000u) ? 1 : 0;
        }
        if (!okI) atomicAnd(&sI, 0);
        if (!okF) atomicAnd(&sF, 0);
        __syncthreads();
        if (tid == 0) g_masktype = sF ? 2 : (sI ? 1 : 0);
    }
}

__global__ void k_scan() {
    __shared__ int s[NN];
    int t = threadIdx.x; // 1024
    s[t] = g_deg[t]; s[t+1024] = g_deg[t+1024];
    __syncthreads();
    for (int off = 1; off < NN; off <<= 1) {
        int v0 = s[t], v1 = s[t+1024];
        int u0 = (t >= off) ? s[t-off] : 0;
        int u1 = ((t+1024) >= off) ? s[t+1024-off] : 0;
        __syncthreads();
        s[t] = v0 + u0; s[t+1024] = v1 + u1;
        __syncthreads();
    }
    g_rowptr[t+1] = s[t];
    g_rowptr[t+1025] = s[t+1024];
    if (t == 0) g_rowptr[0] = 0;
}

// ---------------- persistent kernel ----------------
// smem: sWmix 8192 | sWmsg 4096 | stated 3584 | m2d 3584 | catU 7168 | sLoss 8 | sReadW 64
// gate (compact, 3072 floats: bp*768 + half*384 + g*2) aliases catU[0:3072)
#define SMEM_FLOATS (8192 + 4096 + 3584 + 3584 + 7168 + 8 + 64)
#define SMEM_BYTES  (SMEM_FLOATS * 4)

__global__ __launch_bounds__(384, 2) void k_persist(
    const float* __restrict__ x, const float* __restrict__ targets,
    const void* __restrict__ tmask, const int* __restrict__ ei,
    const float* __restrict__ b_msg, const float* __restrict__ b_mix,
    const float* __restrict__ b_ih, const float* __restrict__ b_hh,
    const float* __restrict__ W_read, const float* __restrict__ b_read)
{
    extern __shared__ float sm[];
    float* sWmix  = sm;                // [k128][h64]
    float* sWmsg  = sWmix + 8192;      // [k64][h64]
    float* stated = sWmsg + 4096;      // [j7][bp4][k64][2]: j*512 + bp*128 + k*2
    float* m2d    = stated + 3584;     // same layout
    float* catU   = m2d + 3584;        // gather cat / gate buf / prologue scratch
    float* sLoss  = catU + 7168;       // [8]
    float* sReadW = sLoss + 8;         // [64]
    float* gate   = catU;              // compact: bp*768 + half*384 + g*2

    const int tid = threadIdx.x;
    const int bid = blockIdx.x;
    const int cnt = (bid < 272) ? 7 : 6;
    const int mt  = g_masktype;
    const float br0 = b_read[0];

    // ---- one-time grid prologue: CSR fill + mask count ----
    {
        int lane = tid & 31;
        int w = bid*12 + (tid >> 5);
        if (w < NN) {
            const int* src = ei;
            const int* dst = ei + EE;
            int off = g_rowptr[w];
            for (int base = 0; base < EE; base += 32) {
                int e = base + lane;
                bool match = (dst[e] == w);
                unsigned bal = __ballot_sync(0xffffffffu, match);
                if (match) {
                    int pos = off + __popc(bal & ((1u << lane) - 1u));
                    g_csrc[pos] = src[e];
                }
                off += __popc(bal);
            }
        }
        int c2 = 0;
        for (size_t i = (size_t)bid*384 + tid; i < (size_t)BB*TT*NN; i += (size_t)NBLK*384)
            c2 += mask_at(tmask, i, mt);
        #pragma unroll
        for (int o = 16; o; o >>= 1) c2 += __shfl_down_sync(0xffffffffu, c2, o);
        int* ish = (int*)catU;
        if (lane == 0) ish[tid >> 5] = c2;
        __syncthreads();
        if (tid == 0) {
            int s = 0;
            #pragma unroll
            for (int i = 0; i < 12; ++i) s += ish[i];
            atomicAdd(&g_maskcnt, s);
        }
        grid_barrier(bid, tid, 1u);
    }

    for (int i = tid; i < 8192; i += 384) sWmix[i] = g_Wmix_t[i];
    for (int i = tid; i < 4096; i += 384) sWmsg[i] = g_Wmsg_t[i];
    for (int i = tid; i < 3584; i += 384) stated[i] = 0.f;
    if (tid < 64) sReadW[tid] = W_read[tid];
    if (tid < 8) sLoss[tid] = 0.f;
    __syncthreads();

    for (int t = 0; t < TT; ++t) {
        const float* __restrict__ mprev = g_m[t & 1];
        float* __restrict__ mnext = g_m[(t + 1) & 1];
        const int na = cnt*64;

        // ---- gather (agg) + x load into catU ----
        for (int task = tid; task < cnt*128; task += 384) {
            if (task < na) {
                int j = task >> 6, r = task & 63;
                int bp = r >> 4, h4 = r & 15;
                int n = bid + j*296;
                int b0 = 2*bp;
                int rs = g_rowptr[n], re = g_rowptr[n+1];
                float4 a0 = make_float4(0.f,0.f,0.f,0.f), a1 = a0;
                #pragma unroll 4
                for (int e = rs; e < re; ++e) {
                    int s = __ldg(&g_csrc[e]);
                    float4 v0 = *(const float4*)&mprev[((size_t)b0*NN + s)*64 + h4*4];
                    float4 v1 = *(const float4*)&mprev[((size_t)(b0+1)*NN + s)*64 + h4*4];
                    a0.x += v0.x; a0.y += v0.y; a0.z += v0.z; a0.w += v0.w;
                    a1.x += v1.x; a1.y += v1.y; a1.z += v1.z; a1.w += v1.w;
                }
                float* d = catU + j*1024 + bp*256 + h4*8;
                d[0]=a0.x; d[1]=a1.x; d[2]=a0.y; d[3]=a1.y;
                d[4]=a0.z; d[5]=a1.z; d[6]=a0.w; d[7]=a1.w;
            } else {
                int tx = task - na;
                int j = tx >> 6, r = tx & 63;
                int bp = r >> 4, f4 = r & 15;
                int n = bid + j*296;
                int b0 = 2*bp;
                float4 v0 = *(const float4*)&x[(((size_t)b0*TT + t)*NN + n)*64 + f4*4];
                float4 v1 = *(const float4*)&x[(((size_t)(b0+1)*TT + t)*NN + n)*64 + f4*4];
                float* d = catU + j*1024 + bp*256 + 128 + f4*8;
                d[0]=v0.x; d[1]=v1.x; d[2]=v0.y; d[3]=v1.y;
                d[4]=v0.z; d[5]=v1.z; d[6]=v0.w; d[7]=v1.w;
            }
        }
        __syncthreads();

        // ---- P2: m2 = Wmix @ cat + b_mix ----
        if (tid < cnt*32) {
            int j = tid >> 5, h2 = tid & 31;
            unsigned long long acc[8];
            #pragma unroll
            for (int i = 0; i < 8; ++i) acc[i] = 0ull;
            const float* vb = catU + j*1024;
            #pragma unroll 2
            for (int k = 0; k < 128; k += 2) {
                float2 wa = *(const float2*)&sWmix[k*64 + h2*2];
                float2 wb = *(const float2*)&sWmix[(k+1)*64 + h2*2];
                unsigned long long Wa0,Wa1,Wb0,Wb1;
                SPLATF(Wa0,wa.x); SPLATF(Wa1,wa.y); SPLATF(Wb0,wb.x); SPLATF(Wb1,wb.y);
                #pragma unroll
                for (int bp = 0; bp < 4; ++bp) {
                    ulonglong2 vv = *(const ulonglong2*)(vb + bp*256 + k*2);
                    FMA2(acc[bp],   Wa0, vv.x); FMA2(acc[bp],   Wb0, vv.y);
                    FMA2(acc[4+bp], Wa1, vv.x); FMA2(acc[4+bp], Wb1, vv.y);
                }
            }
            float bm0 = b_mix[h2*2], bm1 = b_mix[h2*2+1];
            float* mo = m2d + j*512;
            #pragma unroll
            for (int bp = 0; bp < 4; ++bp) {
                float lo, hi;
                UNPK2(lo, hi, acc[bp]);
                mo[bp*128 + h2*4 + 0] = bm0 + lo;
                mo[bp*128 + h2*4 + 1] = bm0 + hi;
                UNPK2(lo, hi, acc[4+bp]);
                mo[bp*128 + h2*4 + 2] = bm1 + lo;
                mo[bp*128 + h2*4 + 3] = bm1 + hi;
            }
        }
        __syncthreads();

        // ---- P3/P4 per node: 2g x 2bp register tile (halves activation LDS) ----
        for (int j = 0; j < cnt; ++j) {
            {
                const int n = bid + j*296;
                const int half = (tid >= 192) ? 1 : 0;
                const int r = tid - half*192;
                const int gp = r >> 1;          // 0..95
                const int bpp = r & 1;          // batch-pair pair: bp {2bpp, 2bpp+1}
                const int g0 = gp*2;
                const uint4* __restrict__ W4 =
                    (const uint4*)((half ? g_Whh : g_Wih) + (size_t)n*12288 + (size_t)g0*64);
                const float* __restrict__ vb = (half ? stated : m2d) + j*512;
                const float* __restrict__ bias = (half ? b_hh : b_ih) + (size_t)n*GG;
                const float bv0 = bias[g0], bv1 = bias[g0+1];
                unsigned long long a00,a01,a10,a11;
                SPLATF(a00,bv0); SPLATF(a01,bv0); SPLATF(a10,bv1); SPLATF(a11,bv1);
                #pragma unroll
                for (int c = 0; c < 2; ++c) {
                    #pragma unroll
                    for (int i = 0; i < 4; ++i) {
                        uint4 w0 = __ldg(W4 + c*4 + i);        // row g0
                        uint4 w1 = __ldg(W4 + 8 + c*4 + i);    // row g0+1
                        unsigned uw0[4] = {w0.x, w0.y, w0.z, w0.w};
                        unsigned uw1[4] = {w1.x, w1.y, w1.z, w1.w};
                        #pragma unroll
                        for (int u = 0; u < 4; ++u) {
                            unsigned long long W00, W01, W10, W11;
                            SPLAT2(W00, uw0[u] << 16);
                            SPLAT2(W01, uw0[u] & 0xFFFF0000u);
                            SPLAT2(W10, uw1[u] << 16);
                            SPLAT2(W11, uw1[u] & 0xFFFF0000u);
                            const float* vp = vb + (c*32 + i*8 + u*2)*2;
                            ulonglong2 vA = *(const ulonglong2*)(vp + (2*bpp)*128);
                            ulonglong2 vB = *(const ulonglong2*)(vp + (2*bpp+1)*128);
                            FMA2(a00, W00, vA.x); FMA2(a00, W01, vA.y);
                            FMA2(a01, W00, vB.x); FMA2(a01, W01, vB.y);
                            FMA2(a10, W10, vA.x); FMA2(a10, W11, vA.y);
                            FMA2(a11, W10, vB.x); FMA2(a11, W11, vB.y);
                        }
                    }
                }
                float* ob = gate + half*384 + g0*2;
                *(unsigned long long*)(ob + (2*bpp)*768)       = a00;
                *(unsigned long long*)(ob + (2*bpp+1)*768)     = a01;
                *(unsigned long long*)(ob + (2*bpp)*768 + 2)   = a10;
                *(unsigned long long*)(ob + (2*bpp+1)*768 + 2) = a11;
            }
            __syncthreads();
            if (tid < 256) {
                int bp = tid >> 6, h = tid & 63;
                const float* gb = gate + bp*768;
                const float* gi_ = gb;          // half 0 at +0
                const float* gh_ = gb + 384;    // half 1 at +384
                int i0 = h*2;
                float ir0 = gi_[i0],     ir1 = gi_[i0+1];
                float iz0 = gi_[i0+128], iz1 = gi_[i0+129];
                float in0 = gi_[i0+256], in1 = gi_[i0+257];
                float hr0 = gh_[i0],     hr1 = gh_[i0+1];
                float hz0 = gh_[i0+128], hz1 = gh_[i0+129];
                float hn0 = gh_[i0+256], hn1 = gh_[i0+257];
                float* sp = stated + j*512 + bp*128 + h*2;
                float s0 = sp[0], s1 = sp[1];
                float r0 = fast_sig(ir0 + hr0);
                float z0 = fast_sig(iz0 + hz0);
                float n0 = fast_tanh(in0 + r0*hn0);
                float r1 = fast_sig(ir1 + hr1);
                float z1 = fast_sig(iz1 + hz1);
                float n1 = fast_tanh(in1 + r1*hn1);
                sp[0] = (1.f-z0)*n0 + z0*s0;
                sp[1] = (1.f-z1)*n1 + z1*s1;
            }
            __syncthreads();
        }

        // ---- P5: direct write to mnext + loss (threads 224..287) ----
        if (tid < cnt*32) {
            int j = tid >> 5, h2 = tid & 31;
            unsigned long long acc[8];
            #pragma unroll
            for (int i = 0; i < 8; ++i) acc[i] = 0ull;
            const float* vb = stated + j*512;
            #pragma unroll 2
            for (int k = 0; k < 64; k += 2) {
                float2 wa = *(const float2*)&sWmsg[k*64 + h2*2];
                float2 wb = *(const float2*)&sWmsg[(k+1)*64 + h2*2];
                unsigned long long Wa0,Wa1,Wb0,Wb1;
                SPLATF(Wa0,wa.x); SPLATF(Wa1,wa.y); SPLATF(Wb0,wb.x); SPLATF(Wb1,wb.y);
                #pragma unroll
                for (int bp = 0; bp < 4; ++bp) {
                    ulonglong2 vv = *(const ulonglong2*)(vb + bp*128 + k*2);
                    FMA2(acc[bp],   Wa0, vv.x); FMA2(acc[bp],   Wb0, vv.y);
                    FMA2(acc[4+bp], Wa1, vv.x); FMA2(acc[4+bp], Wb1, vv.y);
                }
            }
            float bm0 = b_msg[h2*2], bm1 = b_msg[h2*2+1];
            int n = bid + j*296;
            #pragma unroll
            for (int bp = 0; bp < 4; ++bp) {
                float lo, hi, lo2, hi2;
                UNPK2(lo,  hi,  acc[bp]);
                UNPK2(lo2, hi2, acc[4+bp]);
                float2 v0 = make_float2(bm0 + lo,  bm1 + lo2);
                float2 v1 = make_float2(bm0 + hi,  bm1 + hi2);
                *(float2*)&mnext[((size_t)(2*bp)  *NN + n)*64 + 2*h2] = v0;
                *(float2*)&mnext[((size_t)(2*bp+1)*NN + n)*64 + 2*h2] = v1;
            }
        } else if (tid >= 224 && tid < 288) {
            int q = tid - 224, j = q >> 3, b = q & 7;
            float l = 0.f;
            if (j < cnt) {
                int n = bid + j*296;
                float dot = br0;
                const float* sp = stated + j*512 + (b >> 1)*128 + (b & 1);
                #pragma unroll 8
                for (int h = 0; h < 64; ++h) dot = fmaf(sReadW[h], sp[h*2], dot);
                size_t ti = ((size_t)b*TT + t)*NN + n;
                float d = dot - targets[ti];
                l = mask_at(tmask, ti, mt) ? 0.5f*d*d : 0.f;
            }
            l += __shfl_down_sync(0xffffffffu, l, 4, 8);
            l += __shfl_down_sync(0xffffffffu, l, 2, 8);
            l += __shfl_down_sync(0xffffffffu, l, 1, 8);
            if (b == 0 && j < cnt) sLoss[j] += l;
        }

        if (t < TT - 1) grid_barrier(bid, tid, (unsigned)t + 2u);
        else __syncthreads();
    }

    if (tid < cnt) g_losspart[bid + tid*296] = sLoss[tid];
}

// ---------------- finalize ----------------
__global__ void k_final(float* __restrict__ out) {
    __shared__ float sh[256];
    int tid = threadIdx.x;
    float s = 0.f;
    for (int i = tid; i < NN; i += 256) s += g_losspart[i];
    sh[tid] = s; __syncthreads();
    for (int off = 128; off; off >>= 1) { if (tid < off) sh[tid] += sh[tid+off]; __syncthreads(); }
    if (tid == 0) out[0] = sh[0] / (float)g_maskcnt;
}

// ---------------- launch ----------------
extern "C" void kernel_launch(void* const* d_in, const int* in_sizes, int n_in,
                              void* d_out, int out_size) {
    const float* x       = (const float*)d_in[0];
    const float* targets = (const float*)d_in[1];
    const void*  tmask   = (const void*)d_in[2];
    const int*   ei      = (const int*)d_in[3];
    const float* W_msg   = (const float*)d_in[4];
    const float* b_msg   = (const float*)d_in[5];
    const float* W_mix   = (const float*)d_in[6];
    const float* b_mix   = (const float*)d_in[7];
    const float* W_ih    = (const float*)d_in[8];
    const float* W_hh    = (const float*)d_in[9];
    const float* b_ih    = (const float*)d_in[10];
    const float* b_hh    = (const float*)d_in[11];
    const float* W_read  = (const float*)d_in[12];
    const float* b_read  = (const float*)d_in[13];

    cudaFuncSetAttribute(k_persist, cudaFuncAttributeMaxDynamicSharedMemorySize, SMEM_BYTES);

    k_cvt<<<4096, 256>>>(W_ih, W_hh);
    k_init<<<4097, 256>>>(b_msg, (const unsigned*)tmask, W_mix, W_msg, ei);
    k_scan<<<1, 1024>>>();
    k_persist<<<NBLK, 384, SMEM_BYTES>>>(x, targets, tmask, ei, b_msg, b_mix,
                                         b_ih, b_hh, W_read, b_read);
    k_final<<<1, 256>>>((float*)d_out);
}

// round 16
// speedup vs baseline: 1.5248x; 1.5248x over previous
#include <cuda_runtime.h>
#include <cuda_bf16.h>

#define BB 8
#define TT 64
#define NN 2048
#define GG 192
#define EE 32768
#define NBLK 296
#define WSZ (2048ULL*192*64)

// ---------------- device scratch ----------------
__device__ unsigned short g_Wih[WSZ];        // bf16 [n][c8][g192][k8]  (coalesced chunks)
__device__ unsigned short g_Whh[WSZ];
__device__ float g_Wmix_t[128*64];           // [k][h]
__device__ float g_Wmsg_t[64*64];            // [k][h]
__device__ float g_m[2][(size_t)BB*NN*64];   // messages [b][n][h]
__device__ int   g_deg[NN];
__device__ int   g_rowptr[NN+1];
__device__ int   g_csrc[EE];
__device__ float g_losspart[NN];
__device__ int   g_maskcnt;
__device__ int   g_masktype;
__device__ unsigned g_cnt0[37];
__device__ unsigned g_cnt1;
__device__ unsigned g_gen;

__device__ __forceinline__ int mask_at(const void* m, size_t i, int mt) {
    if (mt == 2) return ((const float*)m)[i] != 0.f;
    if (mt == 1) return ((const int*)m)[i]   != 0;
    return ((const unsigned char*)m)[i] != 0;
}

#define FMA2(d, a, b) asm("fma.rn.f32x2 %0, %1, %2, %3;" : "=l"(d) : "l"(a), "l"(b), "l"(d))
#define SPLAT2(d, w)  asm("mov.b64 %0, {%1, %1};" : "=l"(d) : "r"(w))
#define SPLATF(d, f)  asm("mov.b64 %0, {%1, %1};" : "=l"(d) : "f"(f))
#define UNPK2(lo, hi, v) asm("mov.b64 {%0, %1}, %2;" : "=f"(lo), "=f"(hi) : "l"(v))

__device__ __forceinline__ unsigned short f2bf(float f) {
    __nv_bfloat16 h = __float2bfloat16(f);
    return *reinterpret_cast<unsigned short*>(&h);
}
__device__ __forceinline__ float fast_tanh(float x) {
    float y; asm("tanh.approx.f32 %0, %1;" : "=f"(y) : "f"(x)); return y;
}
__device__ __forceinline__ float fast_sig(float x) {
    return 0.5f + 0.5f * fast_tanh(0.5f * x);
}

__device__ __forceinline__ unsigned ld_vol(unsigned* p) {
    unsigned v; asm volatile("ld.volatile.global.u32 %0, [%1];" : "=r"(v) : "l"(p)); return v;
}

// generation-target grid barrier: 296 blocks = 37 groups x 8
__device__ __forceinline__ void grid_barrier(int bid, int tid, unsigned tgt) {
    __syncthreads();
    if (tid == 0) {
        __threadfence();
        unsigned r = atomicAdd(&g_cnt0[bid >> 3], 1u);
        if (r == 7u) {
            unsigned r2 = atomicAdd(&g_cnt1, 1u);
            if (r2 == 36u) {
                g_cnt1 = 0u;
                #pragma unroll
                for (int i = 0; i < 37; ++i) g_cnt0[i] = 0u;
                __threadfence();
                atomicExch(&g_gen, tgt);
            }
        }
        while (ld_vol(&g_gen) < tgt) __nanosleep(64);
        __threadfence();
    }
    __syncthreads();
}

// ---------------- prologue: convert + re-chunk big weights (coalesced both sides) ----
__global__ void k_cvt(const float* __restrict__ Wih, const float* __restrict__ Whh) {
    __shared__ __align__(16) unsigned short tile[12288];
    int n = blockIdx.x;
    int tid = threadIdx.x; // 256
    if (n == 0) {
        for (int i = tid; i < NN; i += 256) g_deg[i] = 0;
        if (tid == 0) {
            g_maskcnt = 0; g_cnt1 = 0u; g_gen = 0u;
            for (int i = 0; i < 37; ++i) g_cnt0[i] = 0u;
        }
    }
    for (int pass = 0; pass < 2; ++pass) {
        const float* W = (pass ? Whh : Wih) + (size_t)n*12288;
        unsigned short* O = (pass ? g_Whh : g_Wih);
        for (int i = tid; i < 12288; i += 256)
            tile[i] = f2bf(W[i]);                       // coalesced fp32 reads
        __syncthreads();
        uint4* Ob = (uint4*)O + (size_t)n*1536;
        for (int q = tid; q < 1536; q += 256) {
            int c = q / 192, g = q - c*192;
            uint4 o = *(const uint4*)&tile[g*64 + c*8]; // 16B-aligned smem read
            Ob[q] = o;                                  // coalesced 16B writes
        }
        __syncthreads();
    }
}

__global__ void k_init(const float* __restrict__ b_msg, const unsigned* __restrict__ maskw,
                       const float* __restrict__ Wmix, const float* __restrict__ Wmsg,
                       const int* __restrict__ ei) {
    int tid = threadIdx.x;
    if (blockIdx.x < 4096) {
        int i = blockIdx.x*256 + tid;
        g_m[0][i] = b_msg[i & 63];
        if (i < NN) g_losspart[i] = 0.f;
        if (i < EE) atomicAdd(&g_deg[ei[EE + i]], 1);   // degree count
    } else {
        for (int i = tid; i < 128*64; i += 256) {
            int k = i >> 6, h = i & 63;
            g_Wmix_t[i] = Wmix[h*128 + k];
        }
        for (int i = tid; i < 64*64; i += 256) {
            int k = i >> 6, h = i & 63;
            g_Wmsg_t[i] = Wmsg[h*64 + k];
        }
        __shared__ int sI, sF;
        if (tid == 0) { sI = 1; sF = 1; }
        __syncthreads();
        int okI = 1, okF = 1;
        for (int i = tid; i < 4096; i += 256) {
            unsigned v = maskw[i];
            okI &= (v <= 1u) ? 1 : 0;
            okF &= (v == 0u || v == 0x3F800000u) ? 1 : 0;
        }
        if (!okI) atomicAnd(&sI, 0);
        if (!okF) atomicAnd(&sF, 0);
        __syncthreads();
        if (tid == 0) g_masktype = sF ? 2 : (sI ? 1 : 0);
    }
}

__global__ void k_scan() {
    __shared__ int s[NN];
    int t = threadIdx.x; // 1024
    s[t] = g_deg[t]; s[t+1024] = g_deg[t+1024];
    __syncthreads();
    for (int off = 1; off < NN; off <<= 1) {
        int v0 = s[t], v1 = s[t+1024];
        int u0 = (t >= off) ? s[t-off] : 0;
        int u1 = ((t+1024) >= off) ? s[t+1024-off] : 0;
        __syncthreads();
        s[t] = v0 + u0; s[t+1024] = v1 + u1;
        __syncthreads();
    }
    g_rowptr[t+1] = s[t];
    g_rowptr[t+1025] = s[t+1024];
    if (t == 0) g_rowptr[0] = 0;
}

// ---------------- persistent kernel ----------------
// smem: sWmix 8192 | sWmsg 4096 | stated 3584 | m2d 3584 | catU 7168 | sLoss 8 | sReadW 64
// gate (compact, 3072 floats: bp*768 + half*384 + g*2) aliases catU[0:3072)
#define SMEM_FLOATS (8192 + 4096 + 3584 + 3584 + 7168 + 8 + 64)
#define SMEM_BYTES  (SMEM_FLOATS * 4)

__global__ __launch_bounds__(384, 2) void k_persist(
    const float* __restrict__ x, const float* __restrict__ targets,
    const void* __restrict__ tmask, const int* __restrict__ ei,
    const float* __restrict__ b_msg, const float* __restrict__ b_mix,
    const float* __restrict__ b_ih, const float* __restrict__ b_hh,
    const float* __restrict__ W_read, const float* __restrict__ b_read)
{
    extern __shared__ float sm[];
    float* sWmix  = sm;                // [k128][h64]
    float* sWmsg  = sWmix + 8192;      // [k64][h64]
    float* stated = sWmsg + 4096;      // [j7][bp4][k64][2]: j*512 + bp*128 + k*2
    float* m2d    = stated + 3584;     // same layout
    float* catU   = m2d + 3584;        // gather cat / gate buf / prologue scratch
    float* sLoss  = catU + 7168;       // [8]
    float* sReadW = sLoss + 8;         // [64]
    float* gate   = catU;              // compact: bp*768 + half*384 + g*2

    const int tid = threadIdx.x;
    const int bid = blockIdx.x;
    const int cnt = (bid < 272) ? 7 : 6;
    const int mt  = g_masktype;
    const float br0 = b_read[0];

    // ---- one-time grid prologue: CSR fill + mask count ----
    {
        int lane = tid & 31;
        int w = bid*12 + (tid >> 5);
        if (w < NN) {
            const int* src = ei;
            const int* dst = ei + EE;
            int off = g_rowptr[w];
            for (int base = 0; base < EE; base += 32) {
                int e = base + lane;
                bool match = (dst[e] == w);
                unsigned bal = __ballot_sync(0xffffffffu, match);
                if (match) {
                    int pos = off + __popc(bal & ((1u << lane) - 1u));
                    g_csrc[pos] = src[e];
                }
                off += __popc(bal);
            }
        }
        int c2 = 0;
        for (size_t i = (size_t)bid*384 + tid; i < (size_t)BB*TT*NN; i += (size_t)NBLK*384)
            c2 += mask_at(tmask, i, mt);
        #pragma unroll
        for (int o = 16; o; o >>= 1) c2 += __shfl_down_sync(0xffffffffu, c2, o);
        int* ish = (int*)catU;
        if (lane == 0) ish[tid >> 5] = c2;
        __syncthreads();
        if (tid == 0) {
            int s = 0;
            #pragma unroll
            for (int i = 0; i < 12; ++i) s += ish[i];
            atomicAdd(&g_maskcnt, s);
        }
        grid_barrier(bid, tid, 1u);
    }

    for (int i = tid; i < 8192; i += 384) sWmix[i] = g_Wmix_t[i];
    for (int i = tid; i < 4096; i += 384) sWmsg[i] = g_Wmsg_t[i];
    for (int i = tid; i < 3584; i += 384) stated[i] = 0.f;
    if (tid < 64) sReadW[tid] = W_read[tid];
    if (tid < 8) sLoss[tid] = 0.f;
    __syncthreads();

    for (int t = 0; t < TT; ++t) {
        const float* __restrict__ mprev = g_m[t & 1];
        float* __restrict__ mnext = g_m[(t + 1) & 1];
        const int na = cnt*64;

        // ---- gather (agg) + x load into catU ----
        for (int task = tid; task < cnt*128; task += 384) {
            if (task < na) {
                int j = task >> 6, r = task & 63;
                int bp = r >> 4, h4 = r & 15;
                int n = bid + j*296;
                int b0 = 2*bp;
                int rs = g_rowptr[n], re = g_rowptr[n+1];
                float4 a0 = make_float4(0.f,0.f,0.f,0.f), a1 = a0;
                #pragma unroll 4
                for (int e = rs; e < re; ++e) {
                    int s = __ldg(&g_csrc[e]);
                    float4 v0 = *(const float4*)&mprev[((size_t)b0*NN + s)*64 + h4*4];
                    float4 v1 = *(const float4*)&mprev[((size_t)(b0+1)*NN + s)*64 + h4*4];
                    a0.x += v0.x; a0.y += v0.y; a0.z += v0.z; a0.w += v0.w;
                    a1.x += v1.x; a1.y += v1.y; a1.z += v1.z; a1.w += v1.w;
                }
                float* d = catU + j*1024 + bp*256 + h4*8;
                d[0]=a0.x; d[1]=a1.x; d[2]=a0.y; d[3]=a1.y;
                d[4]=a0.z; d[5]=a1.z; d[6]=a0.w; d[7]=a1.w;
            } else {
                int tx = task - na;
                int j = tx >> 6, r = tx & 63;
                int bp = r >> 4, f4 = r & 15;
                int n = bid + j*296;
                int b0 = 2*bp;
                float4 v0 = *(const float4*)&x[(((size_t)b0*TT + t)*NN + n)*64 + f4*4];
                float4 v1 = *(const float4*)&x[(((size_t)(b0+1)*TT + t)*NN + n)*64 + f4*4];
                float* d = catU + j*1024 + bp*256 + 128 + f4*8;
                d[0]=v0.x; d[1]=v1.x; d[2]=v0.y; d[3]=v1.y;
                d[4]=v0.z; d[5]=v1.z; d[6]=v0.w; d[7]=v1.w;
            }
        }
        __syncthreads();

        // ---- P2: m2 = Wmix @ cat + b_mix ----
        if (tid < cnt*32) {
            int j = tid >> 5, h2 = tid & 31;
            unsigned long long acc[8];
            #pragma unroll
            for (int i = 0; i < 8; ++i) acc[i] = 0ull;
            const float* vb = catU + j*1024;
            #pragma unroll 2
            for (int k = 0; k < 128; k += 2) {
                float2 wa = *(const float2*)&sWmix[k*64 + h2*2];
                float2 wb = *(const float2*)&sWmix[(k+1)*64 + h2*2];
                unsigned long long Wa0,Wa1,Wb0,Wb1;
                SPLATF(Wa0,wa.x); SPLATF(Wa1,wa.y); SPLATF(Wb0,wb.x); SPLATF(Wb1,wb.y);
                #pragma unroll
                for (int bp = 0; bp < 4; ++bp) {
                    ulonglong2 vv = *(const ulonglong2*)(vb + bp*256 + k*2);
                    FMA2(acc[bp],   Wa0, vv.x); FMA2(acc[bp],   Wb0, vv.y);
                    FMA2(acc[4+bp], Wa1, vv.x); FMA2(acc[4+bp], Wb1, vv.y);
                }
            }
            float bm0 = b_mix[h2*2], bm1 = b_mix[h2*2+1];
            float* mo = m2d + j*512;
            #pragma unroll
            for (int bp = 0; bp < 4; ++bp) {
                float lo, hi;
                UNPK2(lo, hi, acc[bp]);
                mo[bp*128 + h2*4 + 0] = bm0 + lo;
                mo[bp*128 + h2*4 + 1] = bm0 + hi;
                UNPK2(lo, hi, acc[4+bp]);
                mo[bp*128 + h2*4 + 2] = bm1 + lo;
                mo[bp*128 + h2*4 + 3] = bm1 + hi;
            }
        }
        __syncthreads();

        // ---- P3/P4 per node: coalesced chunked weights, one g per thread ----
        for (int j = 0; j < cnt; ++j) {
            {
                const int n = bid + j*296;
                const int half = (tid >= 192) ? 1 : 0;
                const int g = tid - half*192;
                const uint4* __restrict__ W4 =
                    (const uint4*)(half ? g_Whh : g_Wih) + (size_t)n*1536 + g;
                const float* __restrict__ vb = (half ? stated : m2d) + j*512;
                const float bv = (half ? b_hh : b_ih)[n*GG + g];
                unsigned long long acc[4];
                SPLATF(acc[0], bv); SPLATF(acc[1], bv); SPLATF(acc[2], bv); SPLATF(acc[3], bv);
                #pragma unroll
                for (int c = 0; c < 8; ++c) {
                    uint4 w = __ldg(W4 + c*192);     // lanes consecutive -> coalesced 512B
                    unsigned uw[4] = {w.x, w.y, w.z, w.w};
                    #pragma unroll
                    for (int u = 0; u < 4; ++u) {
                        unsigned long long W0, W1;
                        SPLAT2(W0, uw[u] << 16);
                        SPLAT2(W1, uw[u] & 0xFFFF0000u);
                        const float* vp = vb + (c*8 + u*2)*2;
                        #pragma unroll
                        for (int bp = 0; bp < 4; ++bp) {
                            ulonglong2 vv = *(const ulonglong2*)(vp + bp*128);
                            FMA2(acc[bp], W0, vv.x);
                            FMA2(acc[bp], W1, vv.y);
                        }
                    }
                }
                float* ob = gate + half*384 + g*2;
                #pragma unroll
                for (int bp = 0; bp < 4; ++bp)
                    *(unsigned long long*)(ob + bp*768) = acc[bp];
            }
            __syncthreads();
            if (tid < 256) {
                int bp = tid >> 6, h = tid & 63;
                const float* gb = gate + bp*768;
                const float* gi_ = gb;          // half 0 at +0
                const float* gh_ = gb + 384;    // half 1 at +384
                int i0 = h*2;
                float ir0 = gi_[i0],     ir1 = gi_[i0+1];
                float iz0 = gi_[i0+128], iz1 = gi_[i0+129];
                float in0 = gi_[i0+256], in1 = gi_[i0+257];
                float hr0 = gh_[i0],     hr1 = gh_[i0+1];
                float hz0 = gh_[i0+128], hz1 = gh_[i0+129];
                float hn0 = gh_[i0+256], hn1 = gh_[i0+257];
                float* sp = stated + j*512 + bp*128 + h*2;
                float s0 = sp[0], s1 = sp[1];
                float r0 = fast_sig(ir0 + hr0);
                float z0 = fast_sig(iz0 + hz0);
                float n0 = fast_tanh(in0 + r0*hn0);
                float r1 = fast_sig(ir1 + hr1);
                float z1 = fast_sig(iz1 + hz1);
                float n1 = fast_tanh(in1 + r1*hn1);
                sp[0] = (1.f-z0)*n0 + z0*s0;
                sp[1] = (1.f-z1)*n1 + z1*s1;
            }
            __syncthreads();
        }

        // ---- P5: direct write to mnext + loss (threads 224..287) ----
        if (tid < cnt*32) {
            int j = tid >> 5, h2 = tid & 31;
            unsigned long long acc[8];
            #pragma unroll
            for (int i = 0; i < 8; ++i) acc[i] = 0ull;
            const float* vb = stated + j*512;
            #pragma unroll 2
            for (int k = 0; k < 64; k += 2) {
                float2 wa = *(const float2*)&sWmsg[k*64 + h2*2];
                float2 wb = *(const float2*)&sWmsg[(k+1)*64 + h2*2];
                unsigned long long Wa0,Wa1,Wb0,Wb1;
                SPLATF(Wa0,wa.x); SPLATF(Wa1,wa.y); SPLATF(Wb0,wb.x); SPLATF(Wb1,wb.y);
                #pragma unroll
                for (int bp = 0; bp < 4; ++bp) {
                    ulonglong2 vv = *(const ulonglong2*)(vb + bp*128 + k*2);
                    FMA2(acc[bp],   Wa0, vv.x); FMA2(acc[bp],   Wb0, vv.y);
                    FMA2(acc[4+bp], Wa1, vv.x); FMA2(acc[4+bp], Wb1, vv.y);
                }
            }
            float bm0 = b_msg[h2*2], bm1 = b_msg[h2*2+1];
            int n = bid + j*296;
            #pragma unroll
            for (int bp = 0; bp < 4; ++bp) {
                float lo, hi, lo2, hi2;
                UNPK2(lo,  hi,  acc[bp]);
                UNPK2(lo2, hi2, acc[4+bp]);
                float2 v0 = make_float2(bm0 + lo,  bm1 + lo2);
                float2 v1 = make_float2(bm0 + hi,  bm1 + hi2);
                *(float2*)&mnext[((size_t)(2*bp)  *NN + n)*64 + 2*h2] = v0;
                *(float2*)&mnext[((size_t)(2*bp+1)*NN + n)*64 + 2*h2] = v1;
            }
        } else if (tid >= 224 && tid < 288) {
            int q = tid - 224, j = q >> 3, b = q & 7;
            float l = 0.f;
            if (j < cnt) {
                int n = bid + j*296;
                float dot = br0;
                const float* sp = stated + j*512 + (b >> 1)*128 + (b & 1);
                #pragma unroll 8
                for (int h = 0; h < 64; ++h) dot = fmaf(sReadW[h], sp[h*2], dot);
                size_t ti = ((size_t)b*TT + t)*NN + n;
                float d = dot - targets[ti];
                l = mask_at(tmask, ti, mt) ? 0.5f*d*d : 0.f;
            }
            l += __shfl_down_sync(0xffffffffu, l, 4, 8);
            l += __shfl_down_sync(0xffffffffu, l, 2, 8);
            l += __shfl_down_sync(0xffffffffu, l, 1, 8);
            if (b == 0 && j < cnt) sLoss[j] += l;
        }

        if (t < TT - 1) grid_barrier(bid, tid, (unsigned)t + 2u);
        else __syncthreads();
    }

    if (tid < cnt) g_losspart[bid + tid*296] = sLoss[tid];
}

// ---------------- finalize ----------------
__global__ void k_final(float* __restrict__ out) {
    __shared__ float sh[256];
    int tid = threadIdx.x;
    float s = 0.f;
    for (int i = tid; i < NN; i += 256) s += g_losspart[i];
    sh[tid] = s; __syncthreads();
    for (int off = 128; off; off >>= 1) { if (tid < off) sh[tid] += sh[tid+off]; __syncthreads(); }
    if (tid == 0) out[0] = sh[0] / (float)g_maskcnt;
}

// ---------------- launch ----------------
extern "C" void kernel_launch(void* const* d_in, const int* in_sizes, int n_in,
                              void* d_out, int out_size) {
    const float* x       = (const float*)d_in[0];
    const float* targets = (const float*)d_in[1];
    const void*  tmask   = (const void*)d_in[2];
    const int*   ei      = (const int*)d_in[3];
    const float* W_msg   = (const float*)d_in[4];
    const float* b_msg   = (const float*)d_in[5];
    const float* W_mix   = (const float*)d_in[6];
    const float* b_mix   = (const float*)d_in[7];
    const float* W_ih    = (const float*)d_in[8];
    const float* W_hh    = (const float*)d_in[9];
    const float* b_ih    = (const float*)d_in[10];
    const float* b_hh    = (const float*)d_in[11];
    const float* W_read  = (const float*)d_in[12];
    const float* b_read  = (const float*)d_in[13];

    cudaFuncSetAttribute(k_persist, cudaFuncAttributeMaxDynamicSharedMemorySize, SMEM_BYTES);

    k_cvt<<<2048, 256>>>(W_ih, W_hh);
    k_init<<<4097, 256>>>(b_msg, (const unsigned*)tmask, W_mix, W_msg, ei);
    k_scan<<<1, 1024>>>();
    k_persist<<<NBLK, 384, SMEM_BYTES>>>(x, targets, tmask, ei, b_msg, b_mix,
                                         b_ih, b_hh, W_read, b_read);
    k_final<<<1, 256>>>((float*)d_out);
}

// round 17
// speedup vs baseline: 1.5857x; 1.0400x over previous
#include <cuda_runtime.h>
#include <cuda_bf16.h>

#define BB 8
#define TT 64
#define NN 2048
#define GG 192
#define EE 32768
#define NBLK 296
#define WSZ (2048ULL*192*64)

// ---------------- device scratch ----------------
__device__ unsigned short g_Wih[WSZ];        // bf16 [n][c8][g192][k8]  (coalesced chunks)
__device__ unsigned short g_Whh[WSZ];
__device__ float g_Wmix_t[128*64];           // interleaved [kp64][h64][2]
__device__ float g_Wmsg_t[64*64];            // interleaved [kp32][h64][2]
__device__ float g_m[2][(size_t)BB*NN*64];   // messages [b][n][h]
__device__ int   g_deg[NN];
__device__ int   g_rowptr[NN+1];
__device__ int   g_csrc[EE];
__device__ float g_losspart[NN];
__device__ int   g_maskcnt;
__device__ int   g_masktype;
__device__ unsigned g_cnt0[37];
__device__ unsigned g_cnt1;
__device__ unsigned g_gen;

__device__ __forceinline__ int mask_at(const void* m, size_t i, int mt) {
    if (mt == 2) return ((const float*)m)[i] != 0.f;
    if (mt == 1) return ((const int*)m)[i]   != 0;
    return ((const unsigned char*)m)[i] != 0;
}

#define FMA2(d, a, b) asm("fma.rn.f32x2 %0, %1, %2, %3;" : "=l"(d) : "l"(a), "l"(b), "l"(d))
#define SPLAT2(d, w)  asm("mov.b64 %0, {%1, %1};" : "=l"(d) : "r"(w))
#define SPLATF(d, f)  asm("mov.b64 %0, {%1, %1};" : "=l"(d) : "f"(f))
#define UNPK2(lo, hi, v) asm("mov.b64 {%0, %1}, %2;" : "=f"(lo), "=f"(hi) : "l"(v))

__device__ __forceinline__ unsigned short f2bf(float f) {
    __nv_bfloat16 h = __float2bfloat16(f);
    return *reinterpret_cast<unsigned short*>(&h);
}
__device__ __forceinline__ float fast_tanh(float x) {
    float y; asm("tanh.approx.f32 %0, %1;" : "=f"(y) : "f"(x)); return y;
}
__device__ __forceinline__ float fast_sig(float x) {
    return 0.5f + 0.5f * fast_tanh(0.5f * x);
}

__device__ __forceinline__ unsigned ld_vol(unsigned* p) {
    unsigned v; asm volatile("ld.volatile.global.u32 %0, [%1];" : "=r"(v) : "l"(p)); return v;
}

// generation-target grid barrier: 296 blocks = 37 groups x 8
__device__ __forceinline__ void grid_barrier(int bid, int tid, unsigned tgt) {
    __syncthreads();
    if (tid == 0) {
        __threadfence();
        unsigned r = atomicAdd(&g_cnt0[bid >> 3], 1u);
        if (r == 7u) {
            unsigned r2 = atomicAdd(&g_cnt1, 1u);
            if (r2 == 36u) {
                g_cnt1 = 0u;
                #pragma unroll
                for (int i = 0; i < 37; ++i) g_cnt0[i] = 0u;
                __threadfence();
                atomicExch(&g_gen, tgt);
            }
        }
        while (ld_vol(&g_gen) < tgt) __nanosleep(64);
        __threadfence();
    }
    __syncthreads();
}

// ---------------- prologue: convert + re-chunk big weights (coalesced both sides) ----
__global__ void k_cvt(const float* __restrict__ Wih, const float* __restrict__ Whh) {
    __shared__ __align__(16) unsigned short tile[12288];
    int n = blockIdx.x;
    int tid = threadIdx.x; // 256
    if (n == 0) {
        for (int i = tid; i < NN; i += 256) g_deg[i] = 0;
        if (tid == 0) {
            g_maskcnt = 0; g_cnt1 = 0u; g_gen = 0u;
            for (int i = 0; i < 37; ++i) g_cnt0[i] = 0u;
        }
    }
    for (int pass = 0; pass < 2; ++pass) {
        const float* W = (pass ? Whh : Wih) + (size_t)n*12288;
        unsigned short* O = (pass ? g_Whh : g_Wih);
        for (int i = tid; i < 12288; i += 256)
            tile[i] = f2bf(W[i]);
        __syncthreads();
        uint4* Ob = (uint4*)O + (size_t)n*1536;
        for (int q = tid; q < 1536; q += 256) {
            int c = q / 192, g = q - c*192;
            uint4 o = *(const uint4*)&tile[g*64 + c*8];
            Ob[q] = o;
        }
        __syncthreads();
    }
}

__global__ void k_init(const float* __restrict__ b_msg, const unsigned* __restrict__ maskw,
                       const float* __restrict__ Wmix, const float* __restrict__ Wmsg,
                       const int* __restrict__ ei) {
    int tid = threadIdx.x;
    if (blockIdx.x < 4096) {
        int i = blockIdx.x*256 + tid;
        g_m[0][i] = b_msg[i & 63];
        if (i < NN) g_losspart[i] = 0.f;
        if (i < EE) atomicAdd(&g_deg[ei[EE + i]], 1);
    } else {
        // interleaved small weights: [kp][h][2] so one LDS.128 carries (k,k+1)x(h,h+1)
        for (int i = tid; i < 8192; i += 256) {
            int kp = i >> 7, rst = i & 127, h = rst >> 1, e = rst & 1;
            g_Wmix_t[i] = Wmix[h*128 + 2*kp + e];
        }
        for (int i = tid; i < 4096; i += 256) {
            int kp = i >> 7, rst = i & 127, h = rst >> 1, e = rst & 1;
            g_Wmsg_t[i] = Wmsg[h*64 + 2*kp + e];
        }
        __shared__ int sI, sF;
        if (tid == 0) { sI = 1; sF = 1; }
        __syncthreads();
        int okI = 1, okF = 1;
        for (int i = tid; i < 4096; i += 256) {
            unsigned v = maskw[i];
            okI &= (v <= 1u) ? 1 : 0;
            okF &= (v == 0u || v == 0x3F800000u) ? 1 : 0;
        }
        if (!okI) atomicAnd(&sI, 0);
        if (!okF) atomicAnd(&sF, 0);
        __syncthreads();
        if (tid == 0) g_masktype = sF ? 2 : (sI ? 1 : 0);
    }
}

__global__ void k_scan() {
    __shared__ int s[NN];
    int t = threadIdx.x; // 1024
    s[t] = g_deg[t]; s[t+1024] = g_deg[t+1024];
    __syncthreads();
    for (int off = 1; off < NN; off <<= 1) {
        int v0 = s[t], v1 = s[t+1024];
        int u0 = (t >= off) ? s[t-off] : 0;
        int u1 = ((t+1024) >= off) ? s[t+1024-off] : 0;
        __syncthreads();
        s[t] = v0 + u0; s[t+1024] = v1 + u1;
        __syncthreads();
    }
    g_rowptr[t+1] = s[t];
    g_rowptr[t+1025] = s[t+1024];
    if (t == 0) g_rowptr[0] = 0;
}

// ---------------- persistent kernel ----------------
// smem: sWmix 8192 | sWmsg 4096 | stated 3584 | m2d 3584 | catU 7168 | sLoss 8 | sReadW 64
// gate (compact, 3072 floats: bp*768 + half*384 + g*2) aliases catU[0:3072)
#define SMEM_FLOATS (8192 + 4096 + 3584 + 3584 + 7168 + 8 + 64)
#define SMEM_BYTES  (SMEM_FLOATS * 4)

__global__ __launch_bounds__(384, 2) void k_persist(
    const float* __restrict__ x, const float* __restrict__ targets,
    const void* __restrict__ tmask, const int* __restrict__ ei,
    const float* __restrict__ b_msg, const float* __restrict__ b_mix,
    const float* __restrict__ b_ih, const float* __restrict__ b_hh,
    const float* __restrict__ W_read, const float* __restrict__ b_read)
{
    extern __shared__ float sm[];
    float* sWmix  = sm;                // [kp64][h64][2]
    float* sWmsg  = sWmix + 8192;      // [kp32][h64][2]
    float* stated = sWmsg + 4096;      // [j7][bp4][k64][2]: j*512 + bp*128 + k*2
    float* m2d    = stated + 3584;     // same layout
    float* catU   = m2d + 3584;        // gather cat / gate buf / prologue scratch
    float* sLoss  = catU + 7168;       // [8]
    float* sReadW = sLoss + 8;         // [64]
    float* gate   = catU;              // compact: bp*768 + half*384 + g*2

    const int tid = threadIdx.x;
    const int bid = blockIdx.x;
    const int cnt = (bid < 272) ? 7 : 6;
    const int mt  = g_masktype;
    const float br0 = b_read[0];

    // ---- one-time grid prologue: CSR fill + mask count ----
    {
        int lane = tid & 31;
        int w = bid*12 + (tid >> 5);
        if (w < NN) {
            const int* src = ei;
            const int* dst = ei + EE;
            int off = g_rowptr[w];
            for (int base = 0; base < EE; base += 32) {
                int e = base + lane;
                bool match = (dst[e] == w);
                unsigned bal = __ballot_sync(0xffffffffu, match);
                if (match) {
                    int pos = off + __popc(bal & ((1u << lane) - 1u));
                    g_csrc[pos] = src[e];
                }
                off += __popc(bal);
            }
        }
        int c2 = 0;
        for (size_t i = (size_t)bid*384 + tid; i < (size_t)BB*TT*NN; i += (size_t)NBLK*384)
            c2 += mask_at(tmask, i, mt);
        #pragma unroll
        for (int o = 16; o; o >>= 1) c2 += __shfl_down_sync(0xffffffffu, c2, o);
        int* ish = (int*)catU;
        if (lane == 0) ish[tid >> 5] = c2;
        __syncthreads();
        if (tid == 0) {
            int s = 0;
            #pragma unroll
            for (int i = 0; i < 12; ++i) s += ish[i];
            atomicAdd(&g_maskcnt, s);
        }
        grid_barrier(bid, tid, 1u);
    }

    for (int i = tid; i < 8192; i += 384) sWmix[i] = g_Wmix_t[i];
    for (int i = tid; i < 4096; i += 384) sWmsg[i] = g_Wmsg_t[i];
    for (int i = tid; i < 3584; i += 384) stated[i] = 0.f;
    if (tid < 64) sReadW[tid] = W_read[tid];
    if (tid < 8) sLoss[tid] = 0.f;
    __syncthreads();

    for (int t = 0; t < TT; ++t) {
        const float* __restrict__ mprev = g_m[t & 1];
        float* __restrict__ mnext = g_m[(t + 1) & 1];
        const int na = cnt*64;

        // ---- gather (agg) + x load into catU ----
        for (int task = tid; task < cnt*128; task += 384) {
            if (task < na) {
                int j = task >> 6, r = task & 63;
                int bp = r >> 4, h4 = r & 15;
                int n = bid + j*296;
                int b0 = 2*bp;
                int rs = g_rowptr[n], re = g_rowptr[n+1];
                float4 a0 = make_float4(0.f,0.f,0.f,0.f), a1 = a0;
                #pragma unroll 4
                for (int e = rs; e < re; ++e) {
                    int s = __ldg(&g_csrc[e]);
                    float4 v0 = *(const float4*)&mprev[((size_t)b0*NN + s)*64 + h4*4];
                    float4 v1 = *(const float4*)&mprev[((size_t)(b0+1)*NN + s)*64 + h4*4];
                    a0.x += v0.x; a0.y += v0.y; a0.z += v0.z; a0.w += v0.w;
                    a1.x += v1.x; a1.y += v1.y; a1.z += v1.z; a1.w += v1.w;
                }
                float* d = catU + j*1024 + bp*256 + h4*8;
                d[0]=a0.x; d[1]=a1.x; d[2]=a0.y; d[3]=a1.y;
                d[4]=a0.z; d[5]=a1.z; d[6]=a0.w; d[7]=a1.w;
            } else {
                int tx = task - na;
                int j = tx >> 6, r = tx & 63;
                int bp = r >> 4, f4 = r & 15;
                int n = bid + j*296;
                int b0 = 2*bp;
                float4 v0 = *(const float4*)&x[(((size_t)b0*TT + t)*NN + n)*64 + f4*4];
                float4 v1 = *(const float4*)&x[(((size_t)(b0+1)*TT + t)*NN + n)*64 + f4*4];
                float* d = catU + j*1024 + bp*256 + 128 + f4*8;
                d[0]=v0.x; d[1]=v1.x; d[2]=v0.y; d[3]=v1.y;
                d[4]=v0.z; d[5]=v1.z; d[6]=v0.w; d[7]=v1.w;
            }
        }
        __syncthreads();

        // ---- P2: m2 = Wmix @ cat + b_mix (interleaved weights: 1 LDS.128/iter) ----
        if (tid < cnt*32) {
            int j = tid >> 5, h2 = tid & 31;
            unsigned long long acc[8];
            #pragma unroll
            for (int i = 0; i < 8; ++i) acc[i] = 0ull;
            const float* vb = catU + j*1024;
            #pragma unroll 2
            for (int kp = 0; kp < 64; ++kp) {
                float4 wv = *(const float4*)&sWmix[kp*128 + h2*4];
                unsigned long long Wa0,Wb0,Wa1,Wb1;
                SPLATF(Wa0,wv.x); SPLATF(Wb0,wv.y); SPLATF(Wa1,wv.z); SPLATF(Wb1,wv.w);
                #pragma unroll
                for (int bp = 0; bp < 4; ++bp) {
                    ulonglong2 vv = *(const ulonglong2*)(vb + bp*256 + kp*4);
                    FMA2(acc[bp],   Wa0, vv.x); FMA2(acc[bp],   Wb0, vv.y);
                    FMA2(acc[4+bp], Wa1, vv.x); FMA2(acc[4+bp], Wb1, vv.y);
                }
            }
            float bm0 = b_mix[h2*2], bm1 = b_mix[h2*2+1];
            float* mo = m2d + j*512;
            #pragma unroll
            for (int bp = 0; bp < 4; ++bp) {
                float lo, hi;
                UNPK2(lo, hi, acc[bp]);
                mo[bp*128 + h2*4 + 0] = bm0 + lo;
                mo[bp*128 + h2*4 + 1] = bm0 + hi;
                UNPK2(lo, hi, acc[4+bp]);
                mo[bp*128 + h2*4 + 2] = bm1 + lo;
                mo[bp*128 + h2*4 + 3] = bm1 + hi;
            }
        }
        __syncthreads();

        // ---- P3/P4 per node: 2g x 2bp tile, bpp in high lane bits (broadcast kept) ----
        for (int j = 0; j < cnt; ++j) {
            {
                const int n = bid + j*296;
                const int half = (tid >= 192) ? 1 : 0;
                const int r = tid - half*192;
                const int bpp = (r >= 96) ? 1 : 0;
                const int gp = r - bpp*96;
                const int g0 = gp*2;
                const uint4* __restrict__ W4 =
                    (const uint4*)(half ? g_Whh : g_Wih) + (size_t)n*1536 + g0;
                const float* __restrict__ vb = (half ? stated : m2d) + j*512;
                const float* __restrict__ bias = (half ? b_hh : b_ih) + (size_t)n*GG;
                const float bv0 = bias[g0], bv1 = bias[g0+1];
                unsigned long long a00,a01,a10,a11;
                SPLATF(a00,bv0); SPLATF(a01,bv0); SPLATF(a10,bv1); SPLATF(a11,bv1);
                #pragma unroll
                for (int c = 0; c < 8; ++c) {
                    uint4 w0 = __ldg(W4 + c*192);
                    uint4 w1 = __ldg(W4 + c*192 + 1);
                    unsigned uw0[4] = {w0.x, w0.y, w0.z, w0.w};
                    unsigned uw1[4] = {w1.x, w1.y, w1.z, w1.w};
                    #pragma unroll
                    for (int u = 0; u < 4; ++u) {
                        unsigned long long W00, W01, W10, W11;
                        SPLAT2(W00, uw0[u] << 16);
                        SPLAT2(W01, uw0[u] & 0xFFFF0000u);
                        SPLAT2(W10, uw1[u] << 16);
                        SPLAT2(W11, uw1[u] & 0xFFFF0000u);
                        const float* vp = vb + (c*8 + u*2)*2;
                        ulonglong2 vA = *(const ulonglong2*)(vp + (2*bpp)*128);
                        ulonglong2 vB = *(const ulonglong2*)(vp + (2*bpp+1)*128);
                        FMA2(a00, W00, vA.x); FMA2(a00, W01, vA.y);
                        FMA2(a01, W00, vB.x); FMA2(a01, W01, vB.y);
                        FMA2(a10, W10, vA.x); FMA2(a10, W11, vA.y);
                        FMA2(a11, W10, vB.x); FMA2(a11, W11, vB.y);
                    }
                }
                float* ob = gate + half*384 + g0*2;
                ulonglong2 s0; s0.x = a00; s0.y = a10;
                ulonglong2 s1; s1.x = a01; s1.y = a11;
                *(ulonglong2*)(ob + (2*bpp)*768)   = s0;
                *(ulonglong2*)(ob + (2*bpp+1)*768) = s1;
            }
            __syncthreads();
            if (tid < 256) {
                int bp = tid >> 6, h = tid & 63;
                const float* gb = gate + bp*768;
                const float* gi_ = gb;          // half 0 at +0
                const float* gh_ = gb + 384;    // half 1 at +384
                int i0 = h*2;
                float ir0 = gi_[i0],     ir1 = gi_[i0+1];
                float iz0 = gi_[i0+128], iz1 = gi_[i0+129];
                float in0 = gi_[i0+256], in1 = gi_[i0+257];
                float hr0 = gh_[i0],     hr1 = gh_[i0+1];
                float hz0 = gh_[i0+128], hz1 = gh_[i0+129];
                float hn0 = gh_[i0+256], hn1 = gh_[i0+257];
                float* sp = stated + j*512 + bp*128 + h*2;
                float s0 = sp[0], s1 = sp[1];
                float r0 = fast_sig(ir0 + hr0);
                float z0 = fast_sig(iz0 + hz0);
                float n0 = fast_tanh(in0 + r0*hn0);
                float r1 = fast_sig(ir1 + hr1);
                float z1 = fast_sig(iz1 + hz1);
                float n1 = fast_tanh(in1 + r1*hn1);
                sp[0] = (1.f-z0)*n0 + z0*s0;
                sp[1] = (1.f-z1)*n1 + z1*s1;
            }
            __syncthreads();
        }

        // ---- P5: direct write to mnext + loss (threads 224..287) ----
        if (tid < cnt*32) {
            int j = tid >> 5, h2 = tid & 31;
            unsigned long long acc[8];
            #pragma unroll
            for (int i = 0; i < 8; ++i) acc[i] = 0ull;
            const float* vb = stated + j*512;
            #pragma unroll 2
            for (int kp = 0; kp < 32; ++kp) {
                float4 wv = *(const float4*)&sWmsg[kp*128 + h2*4];
                unsigned long long Wa0,Wb0,Wa1,Wb1;
                SPLATF(Wa0,wv.x); SPLATF(Wb0,wv.y); SPLATF(Wa1,wv.z); SPLATF(Wb1,wv.w);
                #pragma unroll
                for (int bp = 0; bp < 4; ++bp) {
                    ulonglong2 vv = *(const ulonglong2*)(vb + bp*128 + kp*4);
                    FMA2(acc[bp],   Wa0, vv.x); FMA2(acc[bp],   Wb0, vv.y);
                    FMA2(acc[4+bp], Wa1, vv.x); FMA2(acc[4+bp], Wb1, vv.y);
                }
            }
            float bm0 = b_msg[h2*2], bm1 = b_msg[h2*2+1];
            int n = bid + j*296;
            #pragma unroll
            for (int bp = 0; bp < 4; ++bp) {
                float lo, hi, lo2, hi2;
                UNPK2(lo,  hi,  acc[bp]);
                UNPK2(lo2, hi2, acc[4+bp]);
                float2 v0 = make_float2(bm0 + lo,  bm1 + lo2);
                float2 v1 = make_float2(bm0 + hi,  bm1 + hi2);
                *(float2*)&mnext[((size_t)(2*bp)  *NN + n)*64 + 2*h2] = v0;
                *(float2*)&mnext[((size_t)(2*bp+1)*NN + n)*64 + 2*h2] = v1;
            }
        } else if (tid >= 224 && tid < 288) {
            int q = tid - 224, j = q >> 3, b = q & 7;
            float l = 0.f;
            if (j < cnt) {
                int n = bid + j*296;
                float dot = br0;
                const float* sp = stated + j*512 + (b >> 1)*128 + (b & 1);
                #pragma unroll 8
                for (int h = 0; h < 64; ++h) dot = fmaf(sReadW[h], sp[h*2], dot);
                size_t ti = ((size_t)b*TT + t)*NN + n;
                float d = dot - targets[ti];
                l = mask_at(tmask, ti, mt) ? 0.5f*d*d : 0.f;
            }
            l += __shfl_down_sync(0xffffffffu, l, 4, 8);
            l += __shfl_down_sync(0xffffffffu, l, 2, 8);
            l += __shfl_down_sync(0xffffffffu, l, 1, 8);
            if (b == 0 && j < cnt) sLoss[j] += l;
        }

        if (t < TT - 1) grid_barrier(bid, tid, (unsigned)t + 2u);
        else __syncthreads();
    }

    if (tid < cnt) g_losspart[bid + tid*296] = sLoss[tid];
}

// ---------------- finalize ----------------
__global__ void k_final(float* __restrict__ out) {
    __shared__ float sh[256];
    int tid = threadIdx.x;
    float s = 0.f;
    for (int i = tid; i < NN; i += 256) s += g_losspart[i];
    sh[tid] = s; __syncthreads();
    for (int off = 128; off; off >>= 1) { if (tid < off) sh[tid] += sh[tid+off]; __syncthreads(); }
    if (tid == 0) out[0] = sh[0] / (float)g_maskcnt;
}

// ---------------- launch ----------------
extern "C" void kernel_launch(void* const* d_in, const int* in_sizes, int n_in,
                              void* d_out, int out_size) {
    const float* x       = (const float*)d_in[0];
    const float* targets = (const float*)d_in[1];
    const void*  tmask   = (const void*)d_in[2];
    const int*   ei      = (const int*)d_in[3];
    const float* W_msg   = (const float*)d_in[4];
    const float* b_msg   = (const float*)d_in[5];
    const float* W_mix   = (const float*)d_in[6];
    const float* b_mix   = (const float*)d_in[7];
    const float* W_ih    = (const float*)d_in[8];
    const float* W_hh    = (const float*)d_in[9];
    const float* b_ih    = (const float*)d_in[10];
    const float* b_hh    = (const float*)d_in[11];
    const float* W_read  = (const float*)d_in[12];
    const float* b_read  = (const float*)d_in[13];

    cudaFuncSetAttribute(k_persist, cudaFuncAttributeMaxDynamicSharedMemorySize, SMEM_BYTES);

    k_cvt<<<2048, 256>>>(W_ih, W_hh);
    k_init<<<4097, 256>>>(b_msg, (const unsigned*)tmask, W_mix, W_msg, ei);
    k_scan<<<1, 1024>>>();
    k_persist<<<NBLK, 384, SMEM_BYTES>>>(x, targets, tmask, ei, b_msg, b_mix,
                                         b_ih, b_hh, W_read, b_read);
    k_final<<<1, 256>>>((float*)d_out);
}